// round 9
// baseline (speedup 1.0000x reference)
#include <cuda_runtime.h>
#include <cstdint>

// ROI adaptive average pooling: one WARP per (b, s, channel-group-of-4),
// single pass over roi rows with incremental band tracking.
// R9 = R5 structure (16 scalar LDGs in flight per unroll group) minus all
// per-row predication:
//  - loads unpredicated (junk cols >= w never read by phase 2; row clamp
//    min(rr,h-1) for the tail; wide second column clamped to w-1 so STS
//    collisions write identical values)
//  - straddle carry via register renaming: the straddle row at a transition
//    is always the previously processed row -> v[i-1] in-group, 4 MOVs per
//    group across the boundary. No FSELs, no reseed loads.
//
// x:    [B=8, C=64, H=256, W=256] fp32
// rois: [B=8, S=128, 5] int32 (idx, x1, y1, x2, y2); sides in [8,40]
// out:  [B, S*C, 7, 7] fp32; torch adaptive-pool integer bin bounds.

namespace {
constexpr int B  = 8;
constexpr int C  = 64;
constexpr int H  = 256;
constexpr int W  = 256;
constexpr int S  = 128;
constexpr int OH = 7;
constexpr int OW = 7;
constexpr int MAXD = 40;
constexpr int CH = H * W;

constexpr int NCH = 4;                    // channels per warp
constexpr int WPB = 8;                    // warps per block
constexpr int THREADS = WPB * 32;
constexpr int NTASK = B * S * (C / NCH);  // 16384
constexpr int NBLOCK = NTASK / WPB;       // 2048
}

__global__ void __launch_bounds__(THREADS, 6) roi_pool_scan9_kernel(
    const float* __restrict__ x,
    const int*   __restrict__ rois,
    float*       __restrict__ out)
{
    __shared__ float cs_all[WPB][NCH][OH][MAXD];   // 35840 B

    const int lane = threadIdx.x & 31;
    const int warp = threadIdx.x >> 5;

    const int task = blockIdx.x * WPB + warp;
    const int cg   = task & (C / NCH - 1);
    const int bs   = task >> 4;
    const int b    = bs >> 7;
    const int c0   = cg * NCH;

    const int* r = rois + bs * 5;
    const int x1 = r[1];
    const int y1 = r[2];
    const int w  = r[3] - x1;              // [8,40]
    const int h  = r[4] - y1;              // [8,40]

    const float* p0 = x + (size_t)(b * C + c0) * CH + (size_t)y1 * W + x1;

    float (*cs)[OH][MAXD] = cs_all[warp];

    if (w <= 32) {
        // -------- narrow: one lane-set, unroll 4, zero predication --------
        float a0 = 0.f, a1 = 0.f, a2 = 0.f, a3 = 0.f;
        float pc0 = 0.f, pc1 = 0.f, pc2 = 0.f, pc3 = 0.f;   // prev-row carry
        int cur = 0;
        int eyc = (h + 6) / 7;                               // ceil((cur+1)h/7)
        int syn = h / 7;                                     // floor((cur+1)h/7)

        for (int r0 = 0; r0 < h; r0 += 4) {
            float v[4][NCH];
            #pragma unroll
            for (int i = 0; i < 4; ++i) {
                const int rc = min(r0 + i, h - 1);
                const float* p = p0 + rc * W + lane;
                v[i][0] = __ldg(p);
                v[i][1] = __ldg(p + CH);
                v[i][2] = __ldg(p + 2 * CH);
                v[i][3] = __ldg(p + 3 * CH);
            }
            #pragma unroll
            for (int i = 0; i < 4; ++i) {
                const int rr = r0 + i;
                if (rr < h) {                                // warp-uniform
                    if (rr == eyc) {                         // band transition (rare)
                        cs[0][cur][lane] = a0;
                        cs[1][cur][lane] = a1;
                        cs[2][cur][lane] = a2;
                        cs[3][cur][lane] = a3;
                        if (eyc > syn) {                     // straddle: prev row's value
                            a0 = (i == 0) ? pc0 : v[i - 1][0];
                            a1 = (i == 0) ? pc1 : v[i - 1][1];
                            a2 = (i == 0) ? pc2 : v[i - 1][2];
                            a3 = (i == 0) ? pc3 : v[i - 1][3];
                        } else {
                            a0 = 0.f; a1 = 0.f; a2 = 0.f; a3 = 0.f;
                        }
                        ++cur;
                        eyc = ((cur + 1) * h + 6) / 7;
                        syn = ((cur + 1) * h) / 7;
                    }
                    a0 += v[i][0];
                    a1 += v[i][1];
                    a2 += v[i][2];
                    a3 += v[i][3];
                }
            }
            pc0 = v[3][0]; pc1 = v[3][1]; pc2 = v[3][2]; pc3 = v[3][3];
        }
        cs[0][cur][lane] = a0;                               // cur == 6 here
        cs[1][cur][lane] = a1;
        cs[2][cur][lane] = a2;
        cs[3][cur][lane] = a3;
    } else {
        // -------- wide (33..40): two lane-sets, unroll 2, clamped col2 --------
        const int col2 = min(lane + 32, w - 1);              // duplicate col w-1
        float a0 = 0.f, a1 = 0.f, a2 = 0.f, a3 = 0.f;
        float b0 = 0.f, b1 = 0.f, b2 = 0.f, b3 = 0.f;
        float pa0 = 0.f, pa1 = 0.f, pa2 = 0.f, pa3 = 0.f;
        float pb0 = 0.f, pb1 = 0.f, pb2 = 0.f, pb3 = 0.f;
        int cur = 0;
        int eyc = (h + 6) / 7;
        int syn = h / 7;

        for (int r0 = 0; r0 < h; r0 += 2) {
            float va[2][NCH], vb[2][NCH];
            #pragma unroll
            for (int i = 0; i < 2; ++i) {
                const int rc = min(r0 + i, h - 1);
                const float* p = p0 + rc * W;
                va[i][0] = __ldg(p + lane);
                va[i][1] = __ldg(p + CH + lane);
                va[i][2] = __ldg(p + 2 * CH + lane);
                va[i][3] = __ldg(p + 3 * CH + lane);
                vb[i][0] = __ldg(p + col2);
                vb[i][1] = __ldg(p + CH + col2);
                vb[i][2] = __ldg(p + 2 * CH + col2);
                vb[i][3] = __ldg(p + 3 * CH + col2);
            }
            #pragma unroll
            for (int i = 0; i < 2; ++i) {
                const int rr = r0 + i;
                if (rr < h) {
                    if (rr == eyc) {
                        cs[0][cur][lane] = a0;
                        cs[1][cur][lane] = a1;
                        cs[2][cur][lane] = a2;
                        cs[3][cur][lane] = a3;
                        cs[0][cur][col2] = b0;               // dup-value collisions safe
                        cs[1][cur][col2] = b1;
                        cs[2][cur][col2] = b2;
                        cs[3][cur][col2] = b3;
                        if (eyc > syn) {
                            a0 = (i == 0) ? pa0 : va[i - 1][0];
                            a1 = (i == 0) ? pa1 : va[i - 1][1];
                            a2 = (i == 0) ? pa2 : va[i - 1][2];
                            a3 = (i == 0) ? pa3 : va[i - 1][3];
                            b0 = (i == 0) ? pb0 : vb[i - 1][0];
                            b1 = (i == 0) ? pb1 : vb[i - 1][1];
                            b2 = (i == 0) ? pb2 : vb[i - 1][2];
                            b3 = (i == 0) ? pb3 : vb[i - 1][3];
                        } else {
                            a0 = 0.f; a1 = 0.f; a2 = 0.f; a3 = 0.f;
                            b0 = 0.f; b1 = 0.f; b2 = 0.f; b3 = 0.f;
                        }
                        ++cur;
                        eyc = ((cur + 1) * h + 6) / 7;
                        syn = ((cur + 1) * h) / 7;
                    }
                    a0 += va[i][0]; a1 += va[i][1]; a2 += va[i][2]; a3 += va[i][3];
                    b0 += vb[i][0]; b1 += vb[i][1]; b2 += vb[i][2]; b3 += vb[i][3];
                }
            }
            pa0 = va[1][0]; pa1 = va[1][1]; pa2 = va[1][2]; pa3 = va[1][3];
            pb0 = vb[1][0]; pb1 = vb[1][1]; pb2 = vb[1][2]; pb3 = vb[1][3];
        }
        cs[0][cur][lane] = a0;
        cs[1][cur][lane] = a1;
        cs[2][cur][lane] = a2;
        cs[3][cur][lane] = a3;
        cs[0][cur][col2] = b0;
        cs[1][cur][col2] = b1;
        cs[2][cur][col2] = b2;
        cs[3][cur][col2] = b3;
    }
    __syncwarp();

    // ---- phase 2: bins from column sums, 4 channels per lane-task ----
    float* obase = out + (size_t)(bs * C + c0) * (OH * OW);
    for (int t = lane; t < OH * OW; t += 32) {
        const int oy = t / OW;
        const int ox = t - oy * OW;

        const int sx = (ox * w) / OW;
        const int ex = ((ox + 1) * w + (OW - 1)) / OW;
        const int sy = (oy * h) / OH;
        const int ey = ((oy + 1) * h + (OH - 1)) / OH;

        float q0 = 0.f, q1 = 0.f, q2 = 0.f, q3 = 0.f;
        #pragma unroll 4
        for (int xx = sx; xx < ex; ++xx) {
            q0 += cs[0][oy][xx];
            q1 += cs[1][oy][xx];
            q2 += cs[2][oy][xx];
            q3 += cs[3][oy][xx];
        }

        const float inv = 1.0f / (float)((ey - sy) * (ex - sx));
        obase[t]               = q0 * inv;
        obase[t +     OH * OW] = q1 * inv;
        obase[t + 2 * OH * OW] = q2 * inv;
        obase[t + 3 * OH * OW] = q3 * inv;
    }
}

extern "C" void kernel_launch(void* const* d_in, const int* in_sizes, int n_in,
                              void* d_out, int out_size)
{
    const float* x    = (const float*)d_in[0];
    const int*   rois = (const int*)d_in[1];
    float*       out  = (float*)d_out;

    roi_pool_scan9_kernel<<<NBLOCK, THREADS>>>(x, rois, out);
}

// round 10
// speedup vs baseline: 1.8621x; 1.8621x over previous
#include <cuda_runtime.h>
#include <cstdint>

// ROI adaptive average pooling: one WARP per (b, s, channel-group-of-4).
// One LDG.128 per lane per row covers 4 channels x 32 window cols:
//   quarter = lane>>3 -> channel c0+quarter
//   k       = lane&7  -> float4 slot, window cols 4k..4k+3
// Window starts at x1 & ~3 (off = x1&3 junk cols skipped in phase 2).
// Band straddle via double accumulator: a += v always; n += v when
// rr >= syn (warp-uniform branch); at transition flush a, a = n, n = 0.
//
// x:    [B=8, C=64, H=256, W=256] fp32
// rois: [B=8, S=128, 5] int32 (idx, x1, y1, x2, y2); sides in [8,40]
// out:  [B, S*C, 7, 7] fp32; torch adaptive-pool integer bin bounds.

namespace {
constexpr int B  = 8;
constexpr int C  = 64;
constexpr int H  = 256;
constexpr int W  = 256;
constexpr int S  = 128;
constexpr int OH = 7;
constexpr int OW = 7;
constexpr int CH = H * W;
constexpr int W4 = W / 4;          // row stride in float4
constexpr int PITCH = 44;          // smem strip cols (aligned window width)

constexpr int NCH = 4;
constexpr int WPB = 8;
constexpr int THREADS = WPB * 32;
constexpr int NTASK = B * S * (C / NCH);  // 16384
constexpr int NBLOCK = NTASK / WPB;       // 2048
}

__device__ __forceinline__ void fadd4(float4& a, const float4& v) {
    a.x += v.x; a.y += v.y; a.z += v.z; a.w += v.w;
}

__global__ void __launch_bounds__(THREADS) roi_pool_f4_kernel(
    const float* __restrict__ x,
    const int*   __restrict__ rois,
    float*       __restrict__ out)
{
    __shared__ float cs_all[WPB][NCH][OH][PITCH];   // 8*4*7*44*4 = 39424 B

    const int lane = threadIdx.x & 31;
    const int warp = threadIdx.x >> 5;

    const int task = blockIdx.x * WPB + warp;
    const int cg   = task & (C / NCH - 1);
    const int bs   = task >> 4;              // b*S + s
    const int b    = bs >> 7;
    const int c0   = cg * NCH;

    const int* r = rois + bs * 5;
    const int x1 = r[1];
    const int y1 = r[2];
    const int w  = r[3] - x1;                // [8,40]
    const int h  = r[4] - y1;                // [8,40]

    const int off = x1 & 3;
    const int x1a = x1 - off;

    const int quarter = lane >> 3;           // channel within group
    const int k       = lane & 7;            // float4 slot: cols 4k..4k+3

    const float4* rowp = reinterpret_cast<const float4*>(
        x + (size_t)(b * C + c0 + quarter) * CH + (size_t)y1 * W + x1a);

    float (*cs)[OH][PITCH] = cs_all[warp];
    const float4 z4 = make_float4(0.f, 0.f, 0.f, 0.f);

    if (off + w <= 32) {
        // ---------------- narrow: 1 LDG.128/row, unroll 8 ----------------
        float4 a = z4, n = z4;
        int cur = 0;
        int eyc = (h + 6) / 7;                       // ceil((cur+1)h/7)
        int syn = h / 7;                             // floor((cur+1)h/7)
        const float4* p = rowp + k;
        int r0 = 0;

        for (; r0 + 8 <= h; r0 += 8, p += 8 * W4) {
            float4 v[8];
            #pragma unroll
            for (int i = 0; i < 8; ++i)
                v[i] = __ldg(p + i * W4);
            #pragma unroll
            for (int i = 0; i < 8; ++i) {
                const int rr = r0 + i;
                if (rr == eyc) {                     // transition (warp-uniform, rare)
                    *reinterpret_cast<float4*>(&cs[quarter][cur][4 * k]) = a;
                    a = n; n = z4;
                    ++cur;
                    eyc = ((cur + 1) * h + 6) / 7;
                    syn = ((cur + 1) * h) / 7;
                }
                fadd4(a, v[i]);
                if (rr >= syn)                        // straddle row (warp-uniform)
                    fadd4(n, v[i]);
            }
        }
        for (; r0 < h; ++r0, p += W4) {              // tail rows
            float4 v = __ldg(p);
            if (r0 == eyc) {
                *reinterpret_cast<float4*>(&cs[quarter][cur][4 * k]) = a;
                a = n; n = z4;
                ++cur;
                eyc = ((cur + 1) * h + 6) / 7;
                syn = ((cur + 1) * h) / 7;
            }
            fadd4(a, v);
            if (r0 >= syn)
                fadd4(n, v);
        }
        *reinterpret_cast<float4*>(&cs[quarter][6][4 * k]) = a;   // cur==6
    } else {
        // ------- wide (off+w in 33..43): main + 3 ext slots, unroll 4 -------
        const bool ext = (k < 3);
        const float4* p  = rowp + k;
        const float4* pe = rowp + 8 + (ext ? k : 0); // cols 32..43 (always in-row)
        float4 a = z4, n = z4, ae = z4, ne = z4;
        int cur = 0;
        int eyc = (h + 6) / 7;
        int syn = h / 7;
        int r0 = 0;

        for (; r0 + 4 <= h; r0 += 4, p += 4 * W4, pe += 4 * W4) {
            float4 v[4], ve[4];
            #pragma unroll
            for (int i = 0; i < 4; ++i) {
                v[i]  = __ldg(p + i * W4);
                ve[i] = ext ? __ldg(pe + i * W4) : z4;
            }
            #pragma unroll
            for (int i = 0; i < 4; ++i) {
                const int rr = r0 + i;
                if (rr == eyc) {
                    *reinterpret_cast<float4*>(&cs[quarter][cur][4 * k]) = a;
                    if (ext)
                        *reinterpret_cast<float4*>(&cs[quarter][cur][32 + 4 * k]) = ae;
                    a = n; ae = ne; n = z4; ne = z4;
                    ++cur;
                    eyc = ((cur + 1) * h + 6) / 7;
                    syn = ((cur + 1) * h) / 7;
                }
                fadd4(a, v[i]);
                fadd4(ae, ve[i]);
                if (rr >= syn) {
                    fadd4(n, v[i]);
                    fadd4(ne, ve[i]);
                }
            }
        }
        for (; r0 < h; ++r0, p += W4, pe += W4) {
            float4 v  = __ldg(p);
            float4 ve = ext ? __ldg(pe) : z4;
            if (r0 == eyc) {
                *reinterpret_cast<float4*>(&cs[quarter][cur][4 * k]) = a;
                if (ext)
                    *reinterpret_cast<float4*>(&cs[quarter][cur][32 + 4 * k]) = ae;
                a = n; ae = ne; n = z4; ne = z4;
                ++cur;
                eyc = ((cur + 1) * h + 6) / 7;
                syn = ((cur + 1) * h) / 7;
            }
            fadd4(a, v);
            fadd4(ae, ve);
            if (r0 >= syn) {
                fadd4(n, v);
                fadd4(ne, ve);
            }
        }
        *reinterpret_cast<float4*>(&cs[quarter][6][4 * k]) = a;
        if (ext)
            *reinterpret_cast<float4*>(&cs[quarter][6][32 + 4 * k]) = ae;
    }
    __syncwarp();

    // ---- phase 2: bins from column sums (crop col j at smem index off+j) ----
    float* obase = out + (size_t)(bs * C + c0) * (OH * OW);
    for (int t = lane; t < OH * OW; t += 32) {
        const int oy = t / OW;
        const int ox = t - oy * OW;

        const int sx = (ox * w) / OW;
        const int ex = ((ox + 1) * w + (OW - 1)) / OW;
        const int sy = (oy * h) / OH;
        const int ey = ((oy + 1) * h + (OH - 1)) / OH;

        float q0 = 0.f, q1 = 0.f, q2 = 0.f, q3 = 0.f;
        #pragma unroll 4
        for (int xx = off + sx; xx < off + ex; ++xx) {
            q0 += cs[0][oy][xx];
            q1 += cs[1][oy][xx];
            q2 += cs[2][oy][xx];
            q3 += cs[3][oy][xx];
        }

        const float inv = 1.0f / (float)((ey - sy) * (ex - sx));
        obase[t]               = q0 * inv;
        obase[t +     OH * OW] = q1 * inv;
        obase[t + 2 * OH * OW] = q2 * inv;
        obase[t + 3 * OH * OW] = q3 * inv;
    }
}

extern "C" void kernel_launch(void* const* d_in, const int* in_sizes, int n_in,
                              void* d_out, int out_size)
{
    const float* x    = (const float*)d_in[0];
    const int*   rois = (const int*)d_in[1];
    float*       out  = (float*)d_out;

    roi_pool_f4_kernel<<<NBLOCK, THREADS>>>(x, rois, out);
}

// round 11
// speedup vs baseline: 1.9786x; 1.0626x over previous
#include <cuda_runtime.h>
#include <cstdint>

// ROI adaptive average pooling: one WARP per (b, s, channel-group-of-4).
// R11 = R10 (LDG.128 lane mapping, double-accumulator straddle) with
// __launch_bounds__(256, 4) to cap regs at 64 -> 4 blocks/SM (occ 33% -> ~60%).
//
// One LDG.128 per lane per row covers 4 channels x 32 window cols:
//   quarter = lane>>3 -> channel c0+quarter
//   k       = lane&7  -> float4 slot, window cols 4k..4k+3
// Window starts at x1 & ~3 (off = x1&3 junk cols skipped in phase 2).
// Band straddle via double accumulator: a += v always; n += v when
// rr >= syn (warp-uniform); at transition flush a, a = n, n = 0.
//
// x:    [B=8, C=64, H=256, W=256] fp32
// rois: [B=8, S=128, 5] int32 (idx, x1, y1, x2, y2); sides in [8,40]
// out:  [B, S*C, 7, 7] fp32; torch adaptive-pool integer bin bounds.

namespace {
constexpr int B  = 8;
constexpr int C  = 64;
constexpr int H  = 256;
constexpr int W  = 256;
constexpr int S  = 128;
constexpr int OH = 7;
constexpr int OW = 7;
constexpr int CH = H * W;
constexpr int W4 = W / 4;          // row stride in float4
constexpr int PITCH = 44;          // smem strip cols (aligned window width)

constexpr int NCH = 4;
constexpr int WPB = 8;
constexpr int THREADS = WPB * 32;
constexpr int NTASK = B * S * (C / NCH);  // 16384
constexpr int NBLOCK = NTASK / WPB;       // 2048
}

__device__ __forceinline__ void fadd4(float4& a, const float4& v) {
    a.x += v.x; a.y += v.y; a.z += v.z; a.w += v.w;
}

__global__ void __launch_bounds__(THREADS, 4) roi_pool_f4o_kernel(
    const float* __restrict__ x,
    const int*   __restrict__ rois,
    float*       __restrict__ out)
{
    __shared__ float cs_all[WPB][NCH][OH][PITCH];   // 8*4*7*44*4 = 39424 B

    const int lane = threadIdx.x & 31;
    const int warp = threadIdx.x >> 5;

    const int task = blockIdx.x * WPB + warp;
    const int cg   = task & (C / NCH - 1);
    const int bs   = task >> 4;              // b*S + s
    const int b    = bs >> 7;
    const int c0   = cg * NCH;

    const int* r = rois + bs * 5;
    const int x1 = r[1];
    const int y1 = r[2];
    const int w  = r[3] - x1;                // [8,40]
    const int h  = r[4] - y1;                // [8,40]

    const int off = x1 & 3;
    const int x1a = x1 - off;

    const int quarter = lane >> 3;           // channel within group
    const int k       = lane & 7;            // float4 slot: cols 4k..4k+3

    const float4* rowp = reinterpret_cast<const float4*>(
        x + (size_t)(b * C + c0 + quarter) * CH + (size_t)y1 * W + x1a);

    float (*cs)[OH][PITCH] = cs_all[warp];
    const float4 z4 = make_float4(0.f, 0.f, 0.f, 0.f);

    if (off + w <= 32) {
        // ---------------- narrow: 1 LDG.128/row, unroll 8 ----------------
        float4 a = z4, n = z4;
        int cur = 0;
        int eyc = (h + 6) / 7;                       // ceil((cur+1)h/7)
        int syn = h / 7;                             // floor((cur+1)h/7)
        const float4* p = rowp + k;
        int r0 = 0;

        for (; r0 + 8 <= h; r0 += 8, p += 8 * W4) {
            float4 v[8];
            #pragma unroll
            for (int i = 0; i < 8; ++i)
                v[i] = __ldg(p + i * W4);
            #pragma unroll
            for (int i = 0; i < 8; ++i) {
                const int rr = r0 + i;
                if (rr == eyc) {                     // transition (warp-uniform, rare)
                    *reinterpret_cast<float4*>(&cs[quarter][cur][4 * k]) = a;
                    a = n; n = z4;
                    ++cur;
                    eyc = ((cur + 1) * h + 6) / 7;
                    syn = ((cur + 1) * h) / 7;
                }
                fadd4(a, v[i]);
                if (rr >= syn)                        // straddle row (warp-uniform)
                    fadd4(n, v[i]);
            }
        }
        for (; r0 < h; ++r0, p += W4) {              // tail rows
            float4 v = __ldg(p);
            if (r0 == eyc) {
                *reinterpret_cast<float4*>(&cs[quarter][cur][4 * k]) = a;
                a = n; n = z4;
                ++cur;
                eyc = ((cur + 1) * h + 6) / 7;
                syn = ((cur + 1) * h) / 7;
            }
            fadd4(a, v);
            if (r0 >= syn)
                fadd4(n, v);
        }
        *reinterpret_cast<float4*>(&cs[quarter][6][4 * k]) = a;   // cur==6
    } else {
        // ------- wide (off+w in 33..43): main + 3 ext slots, unroll 4 -------
        const bool ext = (k < 3);
        const float4* p  = rowp + k;
        const float4* pe = rowp + 8 + (ext ? k : 0); // cols 32..43 (always in-row)
        float4 a = z4, n = z4, ae = z4, ne = z4;
        int cur = 0;
        int eyc = (h + 6) / 7;
        int syn = h / 7;
        int r0 = 0;

        for (; r0 + 4 <= h; r0 += 4, p += 4 * W4, pe += 4 * W4) {
            float4 v[4], ve[4];
            #pragma unroll
            for (int i = 0; i < 4; ++i) {
                v[i]  = __ldg(p + i * W4);
                ve[i] = ext ? __ldg(pe + i * W4) : z4;
            }
            #pragma unroll
            for (int i = 0; i < 4; ++i) {
                const int rr = r0 + i;
                if (rr == eyc) {
                    *reinterpret_cast<float4*>(&cs[quarter][cur][4 * k]) = a;
                    if (ext)
                        *reinterpret_cast<float4*>(&cs[quarter][cur][32 + 4 * k]) = ae;
                    a = n; ae = ne; n = z4; ne = z4;
                    ++cur;
                    eyc = ((cur + 1) * h + 6) / 7;
                    syn = ((cur + 1) * h) / 7;
                }
                fadd4(a, v[i]);
                fadd4(ae, ve[i]);
                if (rr >= syn) {
                    fadd4(n, v[i]);
                    fadd4(ne, ve[i]);
                }
            }
        }
        for (; r0 < h; ++r0, p += W4, pe += W4) {
            float4 v  = __ldg(p);
            float4 ve = ext ? __ldg(pe) : z4;
            if (r0 == eyc) {
                *reinterpret_cast<float4*>(&cs[quarter][cur][4 * k]) = a;
                if (ext)
                    *reinterpret_cast<float4*>(&cs[quarter][cur][32 + 4 * k]) = ae;
                a = n; ae = ne; n = z4; ne = z4;
                ++cur;
                eyc = ((cur + 1) * h + 6) / 7;
                syn = ((cur + 1) * h) / 7;
            }
            fadd4(a, v);
            fadd4(ae, ve);
            if (r0 >= syn) {
                fadd4(n, v);
                fadd4(ne, ve);
            }
        }
        *reinterpret_cast<float4*>(&cs[quarter][6][4 * k]) = a;
        if (ext)
            *reinterpret_cast<float4*>(&cs[quarter][6][32 + 4 * k]) = ae;
    }
    __syncwarp();

    // ---- phase 2: bins from column sums (crop col j at smem index off+j) ----
    float* obase = out + (size_t)(bs * C + c0) * (OH * OW);
    for (int t = lane; t < OH * OW; t += 32) {
        const int oy = t / OW;
        const int ox = t - oy * OW;

        const int sx = (ox * w) / OW;
        const int ex = ((ox + 1) * w + (OW - 1)) / OW;
        const int sy = (oy * h) / OH;
        const int ey = ((oy + 1) * h + (OH - 1)) / OH;

        float q0 = 0.f, q1 = 0.f, q2 = 0.f, q3 = 0.f;
        #pragma unroll 4
        for (int xx = off + sx; xx < off + ex; ++xx) {
            q0 += cs[0][oy][xx];
            q1 += cs[1][oy][xx];
            q2 += cs[2][oy][xx];
            q3 += cs[3][oy][xx];
        }

        const float inv = 1.0f / (float)((ey - sy) * (ex - sx));
        obase[t]               = q0 * inv;
        obase[t +     OH * OW] = q1 * inv;
        obase[t + 2 * OH * OW] = q2 * inv;
        obase[t + 3 * OH * OW] = q3 * inv;
    }
}

extern "C" void kernel_launch(void* const* d_in, const int* in_sizes, int n_in,
                              void* d_out, int out_size)
{
    const float* x    = (const float*)d_in[0];
    const int*   rois = (const int*)d_in[1];
    float*       out  = (float*)d_out;

    roi_pool_f4o_kernel<<<NBLOCK, THREADS>>>(x, rois, out);
}